// round 8
// baseline (speedup 1.0000x reference)
#include <cuda_runtime.h>

// GraphMessagePassing on GB300 (sm_103a) — fp32 with packed f32x2 FMA.
//
// Inputs (metadata order):
//  0 node_features [N,64] f32   1 edge_features [E,16] f32
//  2 edge_index    [2,E]  i32   3 w_m1[80,64] 4 b_m1[64] 5 w_m2[64,64] 6 b_m2[64]
//  7 w_u1[128,64]  8 b_u1[64]   9 w_u2[64,64] 10 b_u2[64]
// Output: [N,64] f32
//
// Pipeline: zero g_agg -> prepack weights (k-pair interleave) ->
//           edge kernel (message MLP + float4 atomic scatter) ->
//           node kernel (update MLP -> d_out)

#define MAX_NODES 50000

typedef unsigned long long u64;

// ---------------- device scratch (no allocation allowed) ----------------
__device__ __align__(16) float  g_agg[(size_t)MAX_NODES * 64];
__device__ __align__(16) float2 g_w1p[40 * 64];   // w_m1 80x64, k-pair packed
__device__ __align__(16) float2 g_w2p[32 * 64];   // w_m2 64x64
__device__ __align__(16) float2 g_u1p[64 * 64];   // w_u1 128x64
__device__ __align__(16) float2 g_u2p[32 * 64];   // w_u2 64x64

// ---------------- helpers ----------------
__device__ __forceinline__ u64 ffma2(u64 a, u64 b, u64 c) {
    u64 d;
    asm("fma.rn.f32x2 %0, %1, %2, %3;" : "=l"(d) : "l"(a), "l"(b), "l"(c));
    return d;
}
__device__ __forceinline__ float hsum(u64 v) {
    return __uint_as_float((unsigned)v) + __uint_as_float((unsigned)(v >> 32));
}

// ---------------- zero aggregation buffer ----------------
__global__ void zero_kernel(int n4) {
    float4* p = (float4*)g_agg;
    for (int i = blockIdx.x * blockDim.x + threadIdx.x; i < n4;
         i += gridDim.x * blockDim.x)
        p[i] = make_float4(0.f, 0.f, 0.f, 0.f);
}

// ---------------- weight prepack: w[k][c] -> pairs (w[2k2][c], w[2k2+1][c]) ----
__global__ void prepack_kernel(const float* __restrict__ w_m1,
                               const float* __restrict__ w_m2,
                               const float* __restrict__ w_u1,
                               const float* __restrict__ w_u2) {
    int i = blockIdx.x * blockDim.x + threadIdx.x;
    if (i < 40 * 64) {
        int k2 = i >> 6, c = i & 63;
        g_w1p[i] = make_float2(w_m1[(2 * k2) * 64 + c], w_m1[(2 * k2 + 1) * 64 + c]);
    } else if (i < 72 * 64) {
        int j = i - 40 * 64, k2 = j >> 6, c = j & 63;
        g_w2p[j] = make_float2(w_m2[(2 * k2) * 64 + c], w_m2[(2 * k2 + 1) * 64 + c]);
    } else if (i < 136 * 64) {
        int j = i - 72 * 64, k2 = j >> 6, c = j & 63;
        g_u1p[j] = make_float2(w_u1[(2 * k2) * 64 + c], w_u1[(2 * k2 + 1) * 64 + c]);
    } else if (i < 168 * 64) {
        int j = i - 136 * 64, k2 = j >> 6, c = j & 63;
        g_u2p[j] = make_float2(w_u2[(2 * k2) * 64 + c], w_u2[(2 * k2 + 1) * 64 + c]);
    }
}

// ---------------- fused 2-layer MLP on one 64-row tile ----------------
// Thread (tc in 0..15, tr in 0..15) computes rows tr*4..tr*4+3, cols tc*4..tc*4+3.
// Layer 1: [64,2*KP1] @ [2*KP1,64] + b1, relu -> Hs[64][68]
// Layer 2: Hs @ [64,64] + b2 -> out (no relu)
template <int KP1, int ASTRIDE>
__device__ __forceinline__ void mlp2_tile(const float* __restrict__ As,
                                          float* __restrict__ Hs,
                                          const float2* __restrict__ w1p,
                                          const float2* __restrict__ w2p,
                                          const float* __restrict__ b1,
                                          const float* __restrict__ b2,
                                          int tc, int tr, float4 out[4]) {
    u64 acc[4][4];
#pragma unroll
    for (int i = 0; i < 4; i++)
#pragma unroll
        for (int j = 0; j < 4; j++) acc[i][j] = 0ull;

    const float* A0 = As + (tr * 4 + 0) * ASTRIDE;
    const float* A1 = As + (tr * 4 + 1) * ASTRIDE;
    const float* A2 = As + (tr * 4 + 2) * ASTRIDE;
    const float* A3 = As + (tr * 4 + 3) * ASTRIDE;

#pragma unroll 4
    for (int k2 = 0; k2 < KP1; ++k2) {
        u64 a[4];
        a[0] = *(const u64*)(A0 + k2 * 2);
        a[1] = *(const u64*)(A1 + k2 * 2);
        a[2] = *(const u64*)(A2 + k2 * 2);
        a[3] = *(const u64*)(A3 + k2 * 2);
        ulonglong2 wa = *(const ulonglong2*)(w1p + k2 * 64 + tc * 4);
        ulonglong2 wb = *(const ulonglong2*)(w1p + k2 * 64 + tc * 4 + 2);
        u64 w[4] = {wa.x, wa.y, wb.x, wb.y};
#pragma unroll
        for (int i = 0; i < 4; i++) {
            u64 ai = a[i];
#pragma unroll
            for (int j = 0; j < 4; j++) acc[i][j] = ffma2(ai, w[j], acc[i][j]);
        }
    }

    float4 bb1 = *(const float4*)(b1 + tc * 4);
#pragma unroll
    for (int i = 0; i < 4; i++) {
        float4 h;
        h.x = fmaxf(hsum(acc[i][0]) + bb1.x, 0.f);
        h.y = fmaxf(hsum(acc[i][1]) + bb1.y, 0.f);
        h.z = fmaxf(hsum(acc[i][2]) + bb1.z, 0.f);
        h.w = fmaxf(hsum(acc[i][3]) + bb1.w, 0.f);
        *(float4*)(Hs + (tr * 4 + i) * 68 + tc * 4) = h;
    }
    __syncthreads();

    // Layer 2: K = 64 -> 32 k-pairs, stride 68
#pragma unroll
    for (int i = 0; i < 4; i++)
#pragma unroll
        for (int j = 0; j < 4; j++) acc[i][j] = 0ull;

    const float* H0 = Hs + (tr * 4 + 0) * 68;
    const float* H1 = Hs + (tr * 4 + 1) * 68;
    const float* H2 = Hs + (tr * 4 + 2) * 68;
    const float* H3 = Hs + (tr * 4 + 3) * 68;

#pragma unroll 4
    for (int k2 = 0; k2 < 32; ++k2) {
        u64 a[4];
        a[0] = *(const u64*)(H0 + k2 * 2);
        a[1] = *(const u64*)(H1 + k2 * 2);
        a[2] = *(const u64*)(H2 + k2 * 2);
        a[3] = *(const u64*)(H3 + k2 * 2);
        ulonglong2 wa = *(const ulonglong2*)(w2p + k2 * 64 + tc * 4);
        ulonglong2 wb = *(const ulonglong2*)(w2p + k2 * 64 + tc * 4 + 2);
        u64 w[4] = {wa.x, wa.y, wb.x, wb.y};
#pragma unroll
        for (int i = 0; i < 4; i++) {
            u64 ai = a[i];
#pragma unroll
            for (int j = 0; j < 4; j++) acc[i][j] = ffma2(ai, w[j], acc[i][j]);
        }
    }

    float4 bb2 = *(const float4*)(b2 + tc * 4);
#pragma unroll
    for (int i = 0; i < 4; i++) {
        out[i].x = hsum(acc[i][0]) + bb2.x;
        out[i].y = hsum(acc[i][1]) + bb2.y;
        out[i].z = hsum(acc[i][2]) + bb2.z;
        out[i].w = hsum(acc[i][3]) + bb2.w;
    }
}

// ---------------- edge kernel: message MLP + atomic scatter ----------------
// dyn smem: As[64][84] + Hs[64][68] = 38912 B
__global__ __launch_bounds__(256) void edge_kernel(
    const float* __restrict__ nf, const float* __restrict__ ef,
    const int* __restrict__ src, const int* __restrict__ dst,
    const float* __restrict__ b1, const float* __restrict__ b2, int E) {
    extern __shared__ float sm[];
    float* As = sm;            // [64][84] (cols 0..79 valid)
    float* Hs = sm + 64 * 84;  // [64][68]
    __shared__ int s_src[64], s_dst[64];

    int tid = threadIdx.x;
    int base = blockIdx.x * 64;

    if (tid < 64) {
        int e = base + tid;
        int ec = (e < E) ? e : (E - 1);
        s_src[tid] = src[ec];
        s_dst[tid] = (e < E) ? dst[ec] : -1;
    }
    __syncthreads();

    // Gather: per row 16 float4 of src-node feats + 4 float4 of edge feats
    for (int idx = tid; idx < 64 * 20; idx += 256) {
        int r = idx / 20, q = idx - r * 20;
        float4 v;
        if (q < 16) {
            v = *(const float4*)&nf[(size_t)s_src[r] * 64 + q * 4];
        } else {
            int e = base + r;
            if (e >= E) e = E - 1;
            v = *(const float4*)&ef[(size_t)e * 16 + (q - 16) * 4];
        }
        *(float4*)&As[r * 84 + q * 4] = v;
    }
    __syncthreads();

    int tc = tid & 15, tr = tid >> 4;
    float4 o[4];
    mlp2_tile<40, 84>(As, Hs, g_w1p, g_w2p, b1, b2, tc, tr, o);

#pragma unroll
    for (int i = 0; i < 4; i++) {
        int d = s_dst[tr * 4 + i];
        if (d >= 0)
            atomicAdd((float4*)&g_agg[(size_t)d * 64 + tc * 4], o[i]);
    }
}

// ---------------- node kernel: update MLP -> out ----------------
// dyn smem: As[64][132] + Hs[64][68] = 51200 B
__global__ __launch_bounds__(256) void node_kernel(
    const float* __restrict__ nf, const float* __restrict__ b1,
    const float* __restrict__ b2, float* __restrict__ out, int N) {
    extern __shared__ float sm[];
    float* As = sm;             // [64][132] (cols 0..127 valid)
    float* Hs = sm + 64 * 132;  // [64][68]

    int tid = threadIdx.x;
    int base = blockIdx.x * 64;

    for (int idx = tid; idx < 64 * 32; idx += 256) {
        int r = idx >> 5, q = idx & 31;
        int n = base + r;
        if (n >= N) n = N - 1;
        float4 v;
        if (q < 16) v = *(const float4*)&nf[(size_t)n * 64 + q * 4];
        else        v = *(const float4*)&g_agg[(size_t)n * 64 + (q - 16) * 4];
        *(float4*)&As[r * 132 + q * 4] = v;
    }
    __syncthreads();

    int tc = tid & 15, tr = tid >> 4;
    float4 o[4];
    mlp2_tile<64, 132>(As, Hs, g_u1p, g_u2p, b1, b2, tc, tr, o);

#pragma unroll
    for (int i = 0; i < 4; i++) {
        int n = base + tr * 4 + i;
        if (n < N)
            *(float4*)&out[(size_t)n * 64 + tc * 4] = o[i];
    }
}

// ---------------- launch ----------------
extern "C" void kernel_launch(void* const* d_in, const int* in_sizes, int n_in,
                              void* d_out, int out_size) {
    const float* nf   = (const float*)d_in[0];
    const float* ef   = (const float*)d_in[1];
    const int*   ei   = (const int*)d_in[2];
    const float* w_m1 = (const float*)d_in[3];
    const float* b_m1 = (const float*)d_in[4];
    const float* w_m2 = (const float*)d_in[5];
    const float* b_m2 = (const float*)d_in[6];
    const float* w_u1 = (const float*)d_in[7];
    const float* b_u1 = (const float*)d_in[8];
    const float* w_u2 = (const float*)d_in[9];
    const float* b_u2 = (const float*)d_in[10];
    float* out = (float*)d_out;

    int N = in_sizes[0] / 64;
    int E = in_sizes[2] / 2;
    const int* src = ei;
    const int* dst = ei + E;

    const int EDGE_SMEM = (64 * 84 + 64 * 68) * 4;   // 38912
    const int NODE_SMEM = (64 * 132 + 64 * 68) * 4;  // 51200
    cudaFuncSetAttribute((const void*)edge_kernel,
                         cudaFuncAttributeMaxDynamicSharedMemorySize, EDGE_SMEM);
    cudaFuncSetAttribute((const void*)node_kernel,
                         cudaFuncAttributeMaxDynamicSharedMemorySize, NODE_SMEM);

    zero_kernel<<<592, 256>>>(N * 16);  // N*64 floats / 4
    prepack_kernel<<<42, 256>>>(w_m1, w_m2, w_u1, w_u2);

    int etiles = (E + 63) / 64;
    edge_kernel<<<etiles, 256, EDGE_SMEM>>>(nf, ef, src, dst, b_m1, b_m2, E);

    int ntiles = (N + 63) / 64;
    node_kernel<<<ntiles, 256, NODE_SMEM>>>(nf, b_u1, b_u2, out, N);
}

// round 13
// speedup vs baseline: 1.0273x; 1.0273x over previous
#include <cuda_runtime.h>
#include <cuda_bf16.h>
#include <cstdint>

// GraphMessagePassing on GB300 (sm_103a via sm_103 PTX target)
// Edge MLP:  warp-level bf16 mma.sync (HMMA) with hi/lo split compensation
// Node MLP:  fp32 f32x2-packed SIMT (known good)
//
// Inputs (metadata order):
//  0 node_features [N,64] f32   1 edge_features [E,16] f32
//  2 edge_index    [2,E]  i32   3 w_m1[80,64] 4 b_m1[64] 5 w_m2[64,64] 6 b_m2[64]
//  7 w_u1[128,64]  8 b_u1[64]   9 w_u2[64,64] 10 b_u2[64]
// Output: [N,64] f32

#define MAX_NODES 50000
typedef unsigned long long u64;

// ---------------- device scratch ----------------
__device__ __align__(16) float  g_agg[(size_t)MAX_NODES * 64];
__device__ __align__(16) float2 g_u1p[64 * 64];   // w_u1 128x64 k-pair packed
__device__ __align__(16) float2 g_u2p[32 * 64];   // w_u2 64x64

// ---------------- PTX helpers ----------------
__device__ __forceinline__ uint32_t smem_u32(const void* p) {
    uint32_t a;
    asm("{ .reg .u64 t; cvta.to.shared.u64 t, %1; cvt.u32.u64 %0, t; }"
        : "=r"(a) : "l"(p));
    return a;
}
__device__ __forceinline__ void ldm_x4(uint32_t* r, uint32_t addr) {
    asm volatile("ldmatrix.sync.aligned.m8n8.x4.shared.b16 {%0,%1,%2,%3}, [%4];"
                 : "=r"(r[0]), "=r"(r[1]), "=r"(r[2]), "=r"(r[3]) : "r"(addr));
}
__device__ __forceinline__ void ldm_x2(uint32_t* r, uint32_t addr) {
    asm volatile("ldmatrix.sync.aligned.m8n8.x2.shared.b16 {%0,%1}, [%2];"
                 : "=r"(r[0]), "=r"(r[1]) : "r"(addr));
}
__device__ __forceinline__ void mma_bf16(float* c, const uint32_t* a,
                                         const uint32_t* b) {
    asm volatile(
        "mma.sync.aligned.m16n8k16.row.col.f32.bf16.bf16.f32 "
        "{%0,%1,%2,%3}, {%4,%5,%6,%7}, {%8,%9}, {%0,%1,%2,%3};"
        : "+f"(c[0]), "+f"(c[1]), "+f"(c[2]), "+f"(c[3])
        : "r"(a[0]), "r"(a[1]), "r"(a[2]), "r"(a[3]), "r"(b[0]), "r"(b[1]));
}
__device__ __forceinline__ void split_bf16(float x, unsigned short& h,
                                           unsigned short& l) {
    __nv_bfloat16 bh = __float2bfloat16_rn(x);
    float r = x - __bfloat162float(bh);
    __nv_bfloat16 bl = __float2bfloat16_rn(r);
    h = __bfloat16_as_ushort(bh);
    l = __bfloat16_as_ushort(bl);
}

// =====================================================================
// Edge kernel: 128 edges/block, bf16 HMMA compensated, float4 RED scatter
// =====================================================================
// SMEM layout (bytes). A/B1 stride 88 halfs (176B), H/B2 stride 72 (144B).
#define OFF_SRC  0
#define OFF_DST  512
#define OFF_AH   1024                    // 128*88*2 = 22528
#define OFF_AL   (OFF_AH + 22528)        // 23552
#define OFF_B1H  (OFF_AL + 22528)        // 46080   64*88*2 = 11264
#define OFF_B1L  (OFF_B1H + 11264)       // 57344
#define OFF_HH   (OFF_B1L + 11264)       // 68608   128*72*2 = 18432
#define OFF_HL   (OFF_HH + 18432)        // 87040
#define OFF_B2H  (OFF_HL + 18432)        // 105472  64*72*2 = 9216
#define OFF_B2L  (OFF_B2H + 9216)        // 114688
#define EDGE_SMEM_TOTAL (OFF_B2L + 9216) // 123904
#define OFF_C    OFF_AH                  // f32 staging 128*68*4 = 34816 (aliases A)

__global__ __launch_bounds__(256, 1) void edge_kernel(
    const float* __restrict__ nf, const float* __restrict__ ef,
    const int* __restrict__ src, const int* __restrict__ dst,
    const float* __restrict__ w_m1, const float* __restrict__ b_m1,
    const float* __restrict__ w_m2, const float* __restrict__ b_m2, int E) {
    extern __shared__ char smc[];
    const uint32_t sb = smem_u32(smc);
    int tid = threadIdx.x;
    int wid = tid >> 5, lane = tid & 31;
    int wm = wid & 3, wn = wid >> 2;   // warp tile: rows wm*32.., cols wn*32..
    int* s_src = (int*)(smc + OFF_SRC);
    int* s_dst = (int*)(smc + OFF_DST);
    int e0 = blockIdx.x * 128;

    if (tid < 128) {
        int e = e0 + tid;
        int ec = (e < E) ? e : (E - 1);
        s_src[tid] = src[ec];
        s_dst[tid] = (e < E) ? dst[ec] : -1;
    }
    __syncthreads();

    // ---- gather A (src node feats 64 + edge feats 16), split hi/lo ----
    for (int idx = tid; idx < 128 * 20; idx += 256) {
        int r = idx / 20, q = idx - r * 20;
        float4 v;
        if (q < 16) {
            v = *(const float4*)&nf[(size_t)s_src[r] * 64 + q * 4];
        } else {
            int e = e0 + r;
            if (e >= E) e = E - 1;
            v = *(const float4*)&ef[(size_t)e * 16 + (q - 16) * 4];
        }
        unsigned short h0, l0, h1, l1, h2, l2, h3, l3;
        split_bf16(v.x, h0, l0); split_bf16(v.y, h1, l1);
        split_bf16(v.z, h2, l2); split_bf16(v.w, h3, l3);
        uint2 hp = make_uint2((uint32_t)h0 | ((uint32_t)h1 << 16),
                              (uint32_t)h2 | ((uint32_t)h3 << 16));
        uint2 lp = make_uint2((uint32_t)l0 | ((uint32_t)l1 << 16),
                              (uint32_t)l2 | ((uint32_t)l3 << 16));
        uint32_t boff = (uint32_t)(r * 88 + q * 4) * 2;
        *(uint2*)(smc + OFF_AH + boff) = hp;
        *(uint2*)(smc + OFF_AL + boff) = lp;
    }
    // ---- B1 = w_m1^T [64n x 80k], stride 88 ----
    for (int idx = tid; idx < 80 * 64; idx += 256) {
        int k = idx >> 6, n = idx & 63;
        unsigned short h, l;
        split_bf16(w_m1[idx], h, l);
        uint32_t boff = (uint32_t)(n * 88 + k) * 2;
        *(unsigned short*)(smc + OFF_B1H + boff) = h;
        *(unsigned short*)(smc + OFF_B1L + boff) = l;
    }
    // ---- B2 = w_m2^T [64n x 64k], stride 72 ----
    for (int idx = tid; idx < 64 * 64; idx += 256) {
        int k = idx >> 6, n = idx & 63;
        unsigned short h, l;
        split_bf16(w_m2[idx], h, l);
        uint32_t boff = (uint32_t)(n * 72 + k) * 2;
        *(unsigned short*)(smc + OFF_B2H + boff) = h;
        *(unsigned short*)(smc + OFF_B2L + boff) = l;
    }
    __syncthreads();

    // ldmatrix lane addressing
    int arow = lane & 15, asel = lane >> 4;           // A: 16 rows, 2 col-halves
    int brow = lane & 7,  bsel = (lane >> 3) & 1;     // B: 8 rows, 2 col-halves

    // ---- layer 1: C1 = A @ B1^T, K=80 ----
    float acc[2][4][4];
#pragma unroll
    for (int mt = 0; mt < 2; mt++)
#pragma unroll
        for (int nt = 0; nt < 4; nt++)
#pragma unroll
            for (int i = 0; i < 4; i++) acc[mt][nt][i] = 0.f;

#pragma unroll
    for (int k0 = 0; k0 < 80; k0 += 16) {
        uint32_t ah[2][4], al[2][4];
#pragma unroll
        for (int mt = 0; mt < 2; mt++) {
            uint32_t boff =
                (uint32_t)((wm * 32 + mt * 16 + arow) * 88 + k0 + asel * 8) * 2;
            ldm_x4(ah[mt], sb + OFF_AH + boff);
            ldm_x4(al[mt], sb + OFF_AL + boff);
        }
        uint32_t bh[4][2], bl[4][2];
#pragma unroll
        for (int nt = 0; nt < 4; nt++) {
            uint32_t boff =
                (uint32_t)((wn * 32 + nt * 8 + brow) * 88 + k0 + bsel * 8) * 2;
            ldm_x2(bh[nt], sb + OFF_B1H + boff);
            ldm_x2(bl[nt], sb + OFF_B1L + boff);
        }
#pragma unroll
        for (int mt = 0; mt < 2; mt++)
#pragma unroll
            for (int nt = 0; nt < 4; nt++) {
                mma_bf16(acc[mt][nt], ah[mt], bh[nt]);
                mma_bf16(acc[mt][nt], ah[mt], bl[nt]);
                mma_bf16(acc[mt][nt], al[mt], bh[nt]);
            }
    }

    // ---- epilogue 1: +bias, relu, split -> H hi/lo in SMEM ----
    int crow = lane >> 2, ccol = (lane & 3) * 2;
#pragma unroll
    for (int nt = 0; nt < 4; nt++) {
        int col = wn * 32 + nt * 8 + ccol;
        float bb0 = b_m1[col], bb1 = b_m1[col + 1];
#pragma unroll
        for (int mt = 0; mt < 2; mt++) {
#pragma unroll
            for (int half = 0; half < 2; half++) {
                int row = wm * 32 + mt * 16 + crow + half * 8;
                float x0 = fmaxf(acc[mt][nt][half * 2 + 0] + bb0, 0.f);
                float x1 = fmaxf(acc[mt][nt][half * 2 + 1] + bb1, 0.f);
                unsigned short h0, l0, h1, l1;
                split_bf16(x0, h0, l0);
                split_bf16(x1, h1, l1);
                uint32_t boff = (uint32_t)(row * 72 + col) * 2;
                *(uint32_t*)(smc + OFF_HH + boff) =
                    (uint32_t)h0 | ((uint32_t)h1 << 16);
                *(uint32_t*)(smc + OFF_HL + boff) =
                    (uint32_t)l0 | ((uint32_t)l1 << 16);
            }
        }
    }
    __syncthreads();

    // ---- layer 2: C2 = H @ B2^T, K=64 ----
#pragma unroll
    for (int mt = 0; mt < 2; mt++)
#pragma unroll
        for (int nt = 0; nt < 4; nt++)
#pragma unroll
            for (int i = 0; i < 4; i++) acc[mt][nt][i] = 0.f;

#pragma unroll
    for (int k0 = 0; k0 < 64; k0 += 16) {
        uint32_t ah[2][4], al[2][4];
#pragma unroll
        for (int mt = 0; mt < 2; mt++) {
            uint32_t boff =
                (uint32_t)((wm * 32 + mt * 16 + arow) * 72 + k0 + asel * 8) * 2;
            ldm_x4(ah[mt], sb + OFF_HH + boff);
            ldm_x4(al[mt], sb + OFF_HL + boff);
        }
        uint32_t bh[4][2], bl[4][2];
#pragma unroll
        for (int nt = 0; nt < 4; nt++) {
            uint32_t boff =
                (uint32_t)((wn * 32 + nt * 8 + brow) * 72 + k0 + bsel * 8) * 2;
            ldm_x2(bh[nt], sb + OFF_B2H + boff);
            ldm_x2(bl[nt], sb + OFF_B2L + boff);
        }
#pragma unroll
        for (int mt = 0; mt < 2; mt++)
#pragma unroll
            for (int nt = 0; nt < 4; nt++) {
                mma_bf16(acc[mt][nt], ah[mt], bh[nt]);
                mma_bf16(acc[mt][nt], ah[mt], bl[nt]);
                mma_bf16(acc[mt][nt], al[mt], bh[nt]);
            }
    }
    __syncthreads();   // layer-1 ldmatrix reads of A region done before C aliases it

    // ---- epilogue 2: +bias -> f32 staging tile (stride 68) ----
#pragma unroll
    for (int nt = 0; nt < 4; nt++) {
        int col = wn * 32 + nt * 8 + ccol;
        float bb0 = b_m2[col], bb1 = b_m2[col + 1];
#pragma unroll
        for (int mt = 0; mt < 2; mt++) {
#pragma unroll
            for (int half = 0; half < 2; half++) {
                int row = wm * 32 + mt * 16 + crow + half * 8;
                float2 v = make_float2(acc[mt][nt][half * 2 + 0] + bb0,
                                       acc[mt][nt][half * 2 + 1] + bb1);
                *(float2*)(smc + OFF_C + (uint32_t)(row * 68 + col) * 4) = v;
            }
        }
    }
    __syncthreads();

    // ---- scatter: float4 atomic add into g_agg[dst] ----
    for (int idx = tid; idx < 128 * 16; idx += 256) {
        int r = idx >> 4, q = idx & 15;
        int d = s_dst[r];
        if (d >= 0) {
            float4 v = *(float4*)(smc + OFF_C + (uint32_t)(r * 68 + q * 4) * 4);
            atomicAdd((float4*)&g_agg[(size_t)d * 64 + q * 4], v);
        }
    }
}

// =====================================================================
// Node path (known-good SIMT f32x2)
// =====================================================================
__device__ __forceinline__ u64 ffma2(u64 a, u64 b, u64 c) {
    u64 d;
    asm("fma.rn.f32x2 %0, %1, %2, %3;" : "=l"(d) : "l"(a), "l"(b), "l"(c));
    return d;
}
__device__ __forceinline__ float hsum(u64 v) {
    return __uint_as_float((unsigned)v) + __uint_as_float((unsigned)(v >> 32));
}

__global__ void zero_kernel(int n4) {
    float4* p = (float4*)g_agg;
    for (int i = blockIdx.x * blockDim.x + threadIdx.x; i < n4;
         i += gridDim.x * blockDim.x)
        p[i] = make_float4(0.f, 0.f, 0.f, 0.f);
}

__global__ void prepack_kernel(const float* __restrict__ w_u1,
                               const float* __restrict__ w_u2) {
    int i = blockIdx.x * blockDim.x + threadIdx.x;
    if (i < 64 * 64) {
        int k2 = i >> 6, c = i & 63;
        g_u1p[i] = make_float2(w_u1[(2 * k2) * 64 + c], w_u1[(2 * k2 + 1) * 64 + c]);
    } else if (i < 96 * 64) {
        int j = i - 64 * 64, k2 = j >> 6, c = j & 63;
        g_u2p[j] = make_float2(w_u2[(2 * k2) * 64 + c], w_u2[(2 * k2 + 1) * 64 + c]);
    }
}

template <int KP1, int ASTRIDE>
__device__ __forceinline__ void mlp2_tile(const float* __restrict__ As,
                                          float* __restrict__ Hs,
                                          const float2* __restrict__ w1p,
                                          const float2* __restrict__ w2p,
                                          const float* __restrict__ b1,
                                          const float* __restrict__ b2,
                                          int tc, int tr, float4 out[4]) {
    u64 acc[4][4];
#pragma unroll
    for (int i = 0; i < 4; i++)
#pragma unroll
        for (int j = 0; j < 4; j++) acc[i][j] = 0ull;

    const float* A0 = As + (tr * 4 + 0) * ASTRIDE;
    const float* A1 = As + (tr * 4 + 1) * ASTRIDE;
    const float* A2 = As + (tr * 4 + 2) * ASTRIDE;
    const float* A3 = As + (tr * 4 + 3) * ASTRIDE;

#pragma unroll 4
    for (int k2 = 0; k2 < KP1; ++k2) {
        u64 a[4];
        a[0] = *(const u64*)(A0 + k2 * 2);
        a[1] = *(const u64*)(A1 + k2 * 2);
        a[2] = *(const u64*)(A2 + k2 * 2);
        a[3] = *(const u64*)(A3 + k2 * 2);
        ulonglong2 wa = *(const ulonglong2*)(w1p + k2 * 64 + tc * 4);
        ulonglong2 wb = *(const ulonglong2*)(w1p + k2 * 64 + tc * 4 + 2);
        u64 w[4] = {wa.x, wa.y, wb.x, wb.y};
#pragma unroll
        for (int i = 0; i < 4; i++) {
            u64 ai = a[i];
#pragma unroll
            for (int j = 0; j < 4; j++) acc[i][j] = ffma2(ai, w[j], acc[i][j]);
        }
    }

    float4 bb1 = *(const float4*)(b1 + tc * 4);
#pragma unroll
    for (int i = 0; i < 4; i++) {
        float4 h;
        h.x = fmaxf(hsum(acc[i][0]) + bb1.x, 0.f);
        h.y = fmaxf(hsum(acc[i][1]) + bb1.y, 0.f);
        h.z = fmaxf(hsum(acc[i][2]) + bb1.z, 0.f);
        h.w = fmaxf(hsum(acc[i][3]) + bb1.w, 0.f);
        *(float4*)(Hs + (tr * 4 + i) * 68 + tc * 4) = h;
    }
    __syncthreads();

#pragma unroll
    for (int i = 0; i < 4; i++)
#pragma unroll
        for (int j = 0; j < 4; j++) acc[i][j] = 0ull;

    const float* H0 = Hs + (tr * 4 + 0) * 68;
    const float* H1 = Hs + (tr * 4 + 1) * 68;
    const float* H2 = Hs + (tr * 4 + 2) * 68;
    const float* H3 = Hs + (tr * 4 + 3) * 68;

#pragma unroll 4
    for (int k2 = 0; k2 < 32; ++k2) {
        u64 a[4];
        a[0] = *(const u64*)(H0 + k2 * 2);
        a[1] = *(const u64*)(H1 + k2 * 2);
        a[2] = *(const u64*)(H2 + k2 * 2);
        a[3] = *(const u64*)(H3 + k2 * 2);
        ulonglong2 wa = *(const ulonglong2*)(w2p + k2 * 64 + tc * 4);
        ulonglong2 wb = *(const ulonglong2*)(w2p + k2 * 64 + tc * 4 + 2);
        u64 w[4] = {wa.x, wa.y, wb.x, wb.y};
#pragma unroll
        for (int i = 0; i < 4; i++) {
            u64 ai = a[i];
#pragma unroll
            for (int j = 0; j < 4; j++) acc[i][j] = ffma2(ai, w[j], acc[i][j]);
        }
    }

    float4 bb2 = *(const float4*)(b2 + tc * 4);
#pragma unroll
    for (int i = 0; i < 4; i++) {
        out[i].x = hsum(acc[i][0]) + bb2.x;
        out[i].y = hsum(acc[i][1]) + bb2.y;
        out[i].z = hsum(acc[i][2]) + bb2.z;
        out[i].w = hsum(acc[i][3]) + bb2.w;
    }
}

__global__ __launch_bounds__(256) void node_kernel(
    const float* __restrict__ nf, const float* __restrict__ b1,
    const float* __restrict__ b2, float* __restrict__ out, int N) {
    extern __shared__ float sm[];
    float* As = sm;             // [64][132]
    float* Hs = sm + 64 * 132;  // [64][68]

    int tid = threadIdx.x;
    int base = blockIdx.x * 64;

    for (int idx = tid; idx < 64 * 32; idx += 256) {
        int r = idx >> 5, q = idx & 31;
        int n = base + r;
        if (n >= N) n = N - 1;
        float4 v;
        if (q < 16) v = *(const float4*)&nf[(size_t)n * 64 + q * 4];
        else        v = *(const float4*)&g_agg[(size_t)n * 64 + (q - 16) * 4];
        *(float4*)&As[r * 132 + q * 4] = v;
    }
    __syncthreads();

    int tc = tid & 15, tr = tid >> 4;
    float4 o[4];
    mlp2_tile<64, 132>(As, Hs, g_u1p, g_u2p, b1, b2, tc, tr, o);

#pragma unroll
    for (int i = 0; i < 4; i++) {
        int n = base + tr * 4 + i;
        if (n < N)
            *(float4*)&out[(size_t)n * 64 + tc * 4] = o[i];
    }
}

// =====================================================================
// launch
// =====================================================================
extern "C" void kernel_launch(void* const* d_in, const int* in_sizes, int n_in,
                              void* d_out, int out_size) {
    const float* nf   = (const float*)d_in[0];
    const float* ef   = (const float*)d_in[1];
    const int*   ei   = (const int*)d_in[2];
    const float* w_m1 = (const float*)d_in[3];
    const float* b_m1 = (const float*)d_in[4];
    const float* w_m2 = (const float*)d_in[5];
    const float* b_m2 = (const float*)d_in[6];
    const float* w_u1 = (const float*)d_in[7];
    const float* b_u1 = (const float*)d_in[8];
    const float* w_u2 = (const float*)d_in[9];
    const float* b_u2 = (const float*)d_in[10];
    float* out = (float*)d_out;

    int N = in_sizes[0] / 64;
    int E = in_sizes[2] / 2;
    const int* src = ei;
    const int* dst = ei + E;

    const int NODE_SMEM = (64 * 132 + 64 * 68) * 4;  // 51200
    cudaFuncSetAttribute((const void*)edge_kernel,
                         cudaFuncAttributeMaxDynamicSharedMemorySize,
                         EDGE_SMEM_TOTAL);
    cudaFuncSetAttribute((const void*)node_kernel,
                         cudaFuncAttributeMaxDynamicSharedMemorySize, NODE_SMEM);

    zero_kernel<<<592, 256>>>(N * 16);
    prepack_kernel<<<24, 256>>>(w_u1, w_u2);

    int etiles = (E + 127) / 128;
    edge_kernel<<<etiles, 256, EDGE_SMEM_TOTAL>>>(nf, ef, src, dst, w_m1, b_m1,
                                                  w_m2, b_m2, E);

    int ntiles = (N + 63) / 64;
    node_kernel<<<ntiles, 256, NODE_SMEM>>>(nf, b_u1, b_u2, out, N);
}

// round 14
// speedup vs baseline: 3.1516x; 3.0679x over previous
#include <cuda_runtime.h>
#include <cstdint>

// GraphMessagePassing on GB300 (sm_103a) — linearity-restructured fp32.
//
// messages = relu(nf[src]@W1n + ef@W1e + b1) @ w_m2 + b_m2
// agg      = segment_sum(messages, dst)
//          = (segment_sum(relu_part)) @ w_m2 + deg*b_m2            [w_m2 linear]
// out      = relu([nf, agg]@w_u1 + b_u1) @ w_u2 + b_u2
//   with agg@Wu1b = relu_sum@(w_m2@Wu1b) + deg*(b_m2@Wu1b) = relu_sum@Wc + deg*bc
//
// Pipeline:
//  1 zero      : g_relu, g_deg
//  2 prepack   : Wc = w_m2@w_u1[64:], bc = b_m2@w_u1[64:], pack k-pair weights
//  3 node_pre  : g_pre = nf@w_m1[:64] + b_m1                [N x 64 GEMM]
//  4 edge      : t = relu(g_pre[src] + ef@w_m1[64:]); RED g_relu[dst]+=t, g_deg[dst]+=1
//  5 node      : out = relu(nf@Wu1a + g_relu@Wc + deg*bc + b_u1) @ w_u2 + b_u2
//
// Inputs (metadata order):
//  0 node_features [N,64] f32   1 edge_features [E,16] f32
//  2 edge_index    [2,E]  i32   3 w_m1[80,64] 4 b_m1[64] 5 w_m2[64,64] 6 b_m2[64]
//  7 w_u1[128,64]  8 b_u1[64]   9 w_u2[64,64] 10 b_u2[64]
// Output: [N,64] f32

#define MAX_NODES 50000
typedef unsigned long long u64;

// ---------------- device scratch ----------------
__device__ __align__(16) float  g_pre[(size_t)MAX_NODES * 64];
__device__ __align__(16) float  g_relu[(size_t)MAX_NODES * 64];
__device__ __align__(16) float  g_deg[MAX_NODES];
__device__ __align__(16) float2 g_w1np[32 * 64];  // w_m1[:64] k-pair packed
__device__ __align__(16) float2 g_u1p[64 * 64];   // [w_u1[:64]; Wc] k-pair packed
__device__ __align__(16) float2 g_u2p[32 * 64];   // w_u2 k-pair packed
__device__ __align__(16) float  g_bc[64];         // b_m2 @ w_u1[64:]

// ---------------- helpers ----------------
__device__ __forceinline__ u64 ffma2(u64 a, u64 b, u64 c) {
    u64 d;
    asm("fma.rn.f32x2 %0, %1, %2, %3;" : "=l"(d) : "l"(a), "l"(b), "l"(c));
    return d;
}
__device__ __forceinline__ u64 pack2(float lo, float hi) {
    return ((u64)__float_as_uint(hi) << 32) | (u64)__float_as_uint(lo);
}
__device__ __forceinline__ float lo2(u64 v) { return __uint_as_float((unsigned)v); }
__device__ __forceinline__ float hi2(u64 v) { return __uint_as_float((unsigned)(v >> 32)); }
__device__ __forceinline__ float hsum(u64 v) { return lo2(v) + hi2(v); }

// ---------------- 1. zero ----------------
__global__ void zero_kernel(int nrelu4, int ndeg4) {
    int i = blockIdx.x * blockDim.x + threadIdx.x;
    float4 z = make_float4(0.f, 0.f, 0.f, 0.f);
    for (int j = i; j < nrelu4; j += gridDim.x * blockDim.x)
        ((float4*)g_relu)[j] = z;
    for (int j = i; j < ndeg4; j += gridDim.x * blockDim.x)
        ((float4*)g_deg)[j] = z;
}

// ---------------- 2. prepack (single block) ----------------
__global__ __launch_bounds__(256) void prepack_kernel(
    const float* __restrict__ w_m1, const float* __restrict__ w_m2,
    const float* __restrict__ b_m2, const float* __restrict__ w_u1,
    const float* __restrict__ w_u2) {
    __shared__ __align__(16) float sA[64 * 64];  // w_m2, then Wc
    __shared__ __align__(16) float sB[64 * 64];  // w_u1 bottom half
    int t = threadIdx.x;

    for (int i = t; i < 1024; i += 256) {
        ((float4*)sA)[i] = ((const float4*)w_m2)[i];
        ((float4*)sB)[i] = ((const float4*)(w_u1 + 64 * 64))[i];
    }
    __syncthreads();

    // Wc[k][c] = sum_j w_m2[k][j] * w_u1[64+j][c]  (into registers first)
    float wc[16];
#pragma unroll
    for (int i = 0; i < 16; i++) {
        int id = t + 256 * i;
        int k = id >> 6, c = id & 63;
        float acc = 0.f;
        for (int j = 0; j < 64; j++) acc += sA[k * 64 + j] * sB[j * 64 + c];
        wc[i] = acc;
    }
    // bc[c] = sum_j b_m2[j] * w_u1[64+j][c]
    float bc = 0.f;
    if (t < 64)
        for (int j = 0; j < 64; j++) bc += b_m2[j] * sB[j * 64 + t];
    __syncthreads();
#pragma unroll
    for (int i = 0; i < 16; i++) sA[t + 256 * i] = wc[i];  // sA := Wc
    if (t < 64) g_bc[t] = bc;
    __syncthreads();

    // pack g_w1np from w_m1 rows 0..63
    for (int i = t; i < 32 * 64; i += 256) {
        int k2 = i >> 6, c = i & 63;
        g_w1np[i] = make_float2(w_m1[(2 * k2) * 64 + c], w_m1[(2 * k2 + 1) * 64 + c]);
    }
    // pack g_u1p: rows 0..63 = w_u1 top, rows 64..127 = Wc
    for (int i = t; i < 64 * 64; i += 256) {
        int k2 = i >> 6, c = i & 63;
        float a, b;
        if (k2 < 32) {
            a = w_u1[(2 * k2) * 64 + c];
            b = w_u1[(2 * k2 + 1) * 64 + c];
        } else {
            a = sA[(2 * k2 - 64) * 64 + c];
            b = sA[(2 * k2 - 63) * 64 + c];
        }
        g_u1p[i] = make_float2(a, b);
    }
    // pack g_u2p from w_u2
    for (int i = t; i < 32 * 64; i += 256) {
        int k2 = i >> 6, c = i & 63;
        g_u2p[i] = make_float2(w_u2[(2 * k2) * 64 + c], w_u2[(2 * k2 + 1) * 64 + c]);
    }
}

// ---------------- 3. node_pre: g_pre = nf @ w_m1[:64] + b_m1 ----------------
__global__ __launch_bounds__(256) void node_pre_kernel(
    const float* __restrict__ nf, const float* __restrict__ b1, int N) {
    __shared__ __align__(16) float As[64 * 68];
    int tid = threadIdx.x;
    int base = blockIdx.x * 64;

    for (int idx = tid; idx < 64 * 16; idx += 256) {
        int r = idx >> 4, q = idx & 15;
        int n = base + r;
        if (n >= N) n = N - 1;
        *(float4*)&As[r * 68 + q * 4] = *(const float4*)&nf[(size_t)n * 64 + q * 4];
    }
    __syncthreads();

    int tc = tid & 15, tr = tid >> 4;
    u64 acc[4][4];
#pragma unroll
    for (int i = 0; i < 4; i++)
#pragma unroll
        for (int j = 0; j < 4; j++) acc[i][j] = 0ull;

    const float* A0 = As + (tr * 4 + 0) * 68;
    const float* A1 = As + (tr * 4 + 1) * 68;
    const float* A2 = As + (tr * 4 + 2) * 68;
    const float* A3 = As + (tr * 4 + 3) * 68;

#pragma unroll 4
    for (int k2 = 0; k2 < 32; ++k2) {
        u64 a[4];
        a[0] = *(const u64*)(A0 + k2 * 2);
        a[1] = *(const u64*)(A1 + k2 * 2);
        a[2] = *(const u64*)(A2 + k2 * 2);
        a[3] = *(const u64*)(A3 + k2 * 2);
        ulonglong2 wa = *(const ulonglong2*)(g_w1np + k2 * 64 + tc * 4);
        ulonglong2 wb = *(const ulonglong2*)(g_w1np + k2 * 64 + tc * 4 + 2);
        u64 w[4] = {wa.x, wa.y, wb.x, wb.y};
#pragma unroll
        for (int i = 0; i < 4; i++) {
            u64 ai = a[i];
#pragma unroll
            for (int j = 0; j < 4; j++) acc[i][j] = ffma2(ai, w[j], acc[i][j]);
        }
    }

    float4 bb = *(const float4*)(b1 + tc * 4);
#pragma unroll
    for (int i = 0; i < 4; i++) {
        int n = base + tr * 4 + i;
        if (n < N) {
            float4 o;
            o.x = hsum(acc[i][0]) + bb.x;
            o.y = hsum(acc[i][1]) + bb.y;
            o.z = hsum(acc[i][2]) + bb.z;
            o.w = hsum(acc[i][3]) + bb.w;
            *(float4*)&g_pre[(size_t)n * 64 + tc * 4] = o;
        }
    }
}

// ---------------- 4. edge kernel ----------------
// 128 edges/block, 256 threads. thread = (eq = t&31) owning edges {eq,+32,+64,+96}
// x (ch = t>>5) owning cols ch*8 .. ch*8+7 (4 f32x2 pairs).
__global__ __launch_bounds__(256) void edge_kernel(
    const float* __restrict__ ef, const int* __restrict__ src,
    const int* __restrict__ dst, const float* __restrict__ w_m1, int E) {
    __shared__ int s_src[128], s_dst[128];
    __shared__ __align__(16) float sW[16 * 64];     // w_m1 rows 64..79
    __shared__ __align__(16) float sEf[128 * 17];   // stride 17 (conflict-free)
    __shared__ __align__(16) float sPre[128 * 65];  // stride 65 (conflict-free)

    int tid = threadIdx.x;
    int e0 = blockIdx.x * 128;

    if (tid < 128) {
        int e = e0 + tid;
        int ec = (e < E) ? e : (E - 1);
        s_src[tid] = src[ec];
        s_dst[tid] = (e < E) ? dst[ec] : -1;
    }
    // stage edge-part weights (rows 64..79 of w_m1): 1024 floats
    for (int i = tid; i < 256; i += 256)
        *(float4*)&sW[i * 4] = *(const float4*)&w_m1[4096 + i * 4];
    __syncthreads();

    // stage edge features [128][16] -> stride 17
    for (int idx = tid; idx < 128 * 4; idx += 256) {
        int r = idx >> 2, q = idx & 3;
        int e = e0 + r;
        if (e >= E) e = E - 1;
        float4 v = *(const float4*)&ef[(size_t)e * 16 + q * 4];
        float* p = &sEf[r * 17 + q * 4];
        p[0] = v.x; p[1] = v.y; p[2] = v.z; p[3] = v.w;
    }
    // stage gathered g_pre rows [128][64] -> stride 65
    for (int idx = tid; idx < 128 * 16; idx += 256) {
        int r = idx >> 4, q = idx & 15;
        float4 v = *(const float4*)&g_pre[(size_t)s_src[r] * 64 + q * 4];
        float* p = &sPre[r * 65 + q * 4];
        p[0] = v.x; p[1] = v.y; p[2] = v.z; p[3] = v.w;
    }
    __syncthreads();

    int eq = tid & 31, ch = tid >> 5;
    u64 acc[4][4];
#pragma unroll
    for (int i = 0; i < 4; i++) {
        int e = eq + 32 * i;
        const float* pr = &sPre[e * 65 + ch * 8];
#pragma unroll
        for (int p = 0; p < 4; p++) acc[i][p] = pack2(pr[2 * p], pr[2 * p + 1]);
    }

#pragma unroll
    for (int k = 0; k < 16; k++) {
        u64 wv[4];
#pragma unroll
        for (int p = 0; p < 4; p++)
            wv[p] = *(const u64*)&sW[k * 64 + ch * 8 + 2 * p];  // broadcast
#pragma unroll
        for (int i = 0; i < 4; i++) {
            float a = sEf[(eq + 32 * i) * 17 + k];
            u64 av = pack2(a, a);
#pragma unroll
            for (int p = 0; p < 4; p++) acc[i][p] = ffma2(av, wv[p], acc[i][p]);
        }
    }

    // relu + scatter (2 x float4 RED per edge per thread) + degree
#pragma unroll
    for (int i = 0; i < 4; i++) {
        int e = eq + 32 * i;
        int d = s_dst[e];
        if (d >= 0) {
            float x0 = fmaxf(lo2(acc[i][0]), 0.f), x1 = fmaxf(hi2(acc[i][0]), 0.f);
            float x2 = fmaxf(lo2(acc[i][1]), 0.f), x3 = fmaxf(hi2(acc[i][1]), 0.f);
            float x4 = fmaxf(lo2(acc[i][2]), 0.f), x5 = fmaxf(hi2(acc[i][2]), 0.f);
            float x6 = fmaxf(lo2(acc[i][3]), 0.f), x7 = fmaxf(hi2(acc[i][3]), 0.f);
            float* gp = &g_relu[(size_t)d * 64 + ch * 8];
            atomicAdd((float4*)gp, make_float4(x0, x1, x2, x3));
            atomicAdd((float4*)(gp + 4), make_float4(x4, x5, x6, x7));
            if (ch == 0) atomicAdd(&g_deg[d], 1.0f);
        }
    }
}

// ---------------- 5. node kernel (update MLP with folded agg) ----------------
__global__ __launch_bounds__(256) void node_kernel(
    const float* __restrict__ nf, const float* __restrict__ b1,
    const float* __restrict__ b2, float* __restrict__ out, int N) {
    extern __shared__ float sm[];
    float* As = sm;             // [64][132]  cols 0..63 nf, 64..127 relu_sum
    float* Hs = sm + 64 * 132;  // [64][68]
    __shared__ float s_deg[64];

    int tid = threadIdx.x;
    int base = blockIdx.x * 64;

    for (int idx = tid; idx < 64 * 32; idx += 256) {
        int r = idx >> 5, q = idx & 31;
        int n = base + r;
        if (n >= N) n = N - 1;
        float4 v;
        if (q < 16) v = *(const float4*)&nf[(size_t)n * 64 + q * 4];
        else        v = *(const float4*)&g_relu[(size_t)n * 64 + (q - 16) * 4];
        *(float4*)&As[r * 132 + q * 4] = v;
    }
    if (tid < 64) {
        int n = base + tid;
        s_deg[tid] = (n < N) ? g_deg[n] : 0.f;
    }
    __syncthreads();

    int tc = tid & 15, tr = tid >> 4;
    u64 acc[4][4];
#pragma unroll
    for (int i = 0; i < 4; i++)
#pragma unroll
        for (int j = 0; j < 4; j++) acc[i][j] = 0ull;

    const float* A0 = As + (tr * 4 + 0) * 132;
    const float* A1 = As + (tr * 4 + 1) * 132;
    const float* A2 = As + (tr * 4 + 2) * 132;
    const float* A3 = As + (tr * 4 + 3) * 132;

#pragma unroll 4
    for (int k2 = 0; k2 < 64; ++k2) {
        u64 a[4];
        a[0] = *(const u64*)(A0 + k2 * 2);
        a[1] = *(const u64*)(A1 + k2 * 2);
        a[2] = *(const u64*)(A2 + k2 * 2);
        a[3] = *(const u64*)(A3 + k2 * 2);
        ulonglong2 wa = *(const ulonglong2*)(g_u1p + k2 * 64 + tc * 4);
        ulonglong2 wb = *(const ulonglong2*)(g_u1p + k2 * 64 + tc * 4 + 2);
        u64 w[4] = {wa.x, wa.y, wb.x, wb.y};
#pragma unroll
        for (int i = 0; i < 4; i++) {
            u64 ai = a[i];
#pragma unroll
            for (int j = 0; j < 4; j++) acc[i][j] = ffma2(ai, w[j], acc[i][j]);
        }
    }

    float4 bb1 = *(const float4*)(b1 + tc * 4);
    float4 bcv = *(const float4*)(g_bc + tc * 4);
#pragma unroll
    for (int i = 0; i < 4; i++) {
        float dg = s_deg[tr * 4 + i];
        float4 h;
        h.x = fmaxf(hsum(acc[i][0]) + bb1.x + dg * bcv.x, 0.f);
        h.y = fmaxf(hsum(acc[i][1]) + bb1.y + dg * bcv.y, 0.f);
        h.z = fmaxf(hsum(acc[i][2]) + bb1.z + dg * bcv.z, 0.f);
        h.w = fmaxf(hsum(acc[i][3]) + bb1.w + dg * bcv.w, 0.f);
        *(float4*)(Hs + (tr * 4 + i) * 68 + tc * 4) = h;
    }
    __syncthreads();

#pragma unroll
    for (int i = 0; i < 4; i++)
#pragma unroll
        for (int j = 0; j < 4; j++) acc[i][j] = 0ull;

    const float* H0 = Hs + (tr * 4 + 0) * 68;
    const float* H1 = Hs + (tr * 4 + 1) * 68;
    const float* H2 = Hs + (tr * 4 + 2) * 68;
    const float* H3 = Hs + (tr * 4 + 3) * 68;

#pragma unroll 4
    for (int k2 = 0; k2 < 32; ++k2) {
        u64 a[4];
        a[0] = *(const u64*)(H0 + k2 * 2);
        a[1] = *(const u64*)(H1 + k2 * 2);
        a[2] = *(const u64*)(H2 + k2 * 2);
        a[3] = *(const u64*)(H3 + k2 * 2);
        ulonglong2 wa = *(const ulonglong2*)(g_u2p + k2 * 64 + tc * 4);
        ulonglong2 wb = *(const ulonglong2*)(g_u2p + k2 * 64 + tc * 4 + 2);
        u64 w[4] = {wa.x, wa.y, wb.x, wb.y};
#pragma unroll
        for (int i = 0; i < 4; i++) {
            u64 ai = a[i];
#pragma unroll
            for (int j = 0; j < 4; j++) acc[i][j] = ffma2(ai, w[j], acc[i][j]);
        }
    }

    float4 bb2 = *(const float4*)(b2 + tc * 4);
#pragma unroll
    for (int i = 0; i < 4; i++) {
        int n = base + tr * 4 + i;
        if (n < N) {
            float4 o;
            o.x = hsum(acc[i][0]) + bb2.x;
            o.y = hsum(acc[i][1]) + bb2.y;
            o.z = hsum(acc[i][2]) + bb2.z;
            o.w = hsum(acc[i][3]) + bb2.w;
            *(float4*)&out[(size_t)n * 64 + tc * 4] = o;
        }
    }
}

// ---------------- launch ----------------
extern "C" void kernel_launch(void* const* d_in, const int* in_sizes, int n_in,
                              void* d_out, int out_size) {
    const float* nf   = (const float*)d_in[0];
    const float* ef   = (const float*)d_in[1];
    const int*   ei   = (const int*)d_in[2];
    const float* w_m1 = (const float*)d_in[3];
    const float* b_m1 = (const float*)d_in[4];
    const float* w_m2 = (const float*)d_in[5];
    const float* b_m2 = (const float*)d_in[6];
    const float* w_u1 = (const float*)d_in[7];
    const float* b_u1 = (const float*)d_in[8];
    const float* w_u2 = (const float*)d_in[9];
    const float* b_u2 = (const float*)d_in[10];
    float* out = (float*)d_out;

    int N = in_sizes[0] / 64;
    int E = in_sizes[2] / 2;
    const int* src = ei;
    const int* dst = ei + E;

    const int NODE_SMEM = (64 * 132 + 64 * 68) * 4;  // 51200
    cudaFuncSetAttribute((const void*)node_kernel,
                         cudaFuncAttributeMaxDynamicSharedMemorySize, NODE_SMEM);

    zero_kernel<<<592, 256>>>(N * 16, (N + 3) / 4);
    prepack_kernel<<<1, 256>>>(w_m1, w_m2, b_m2, w_u1, w_u2);

    int ntiles = (N + 63) / 64;
    node_pre_kernel<<<ntiles, 256>>>(nf, b_m1, N);

    int etiles = (E + 127) / 128;
    edge_kernel<<<etiles, 256>>>(ef, src, dst, w_m1, E);

    node_kernel<<<ntiles, 256, NODE_SMEM>>>(nf, b_u1, b_u2, out, N);
}